// round 7
// baseline (speedup 1.0000x reference)
#include <cuda_runtime.h>
#include <math.h>

// Problem constants
#define NM 100000
#define NS 20000
#define NT 200000
#define CC 64
#define EMT 1000000
#define EST 500000
#define MAXN NT

// ---------------- static device scratch ----------------
__device__ float g_h0[NM * CC];
__device__ float g_h1[NS * CC];
__device__ float g_h2[NT * CC];
__device__ float g_o0[NM * CC];
__device__ float g_o1[NS * CC];
__device__ float g_oT0[NT * CC];
__device__ float g_oT1[NT * CC];
__device__ float g_as[4][MAXN * 2];
__device__ float g_ad[4][MAXN * 2];
__device__ float g_acc[2 * CC];
__device__ float g_w[2];

// CSR scratch (built once per call, reused across 3 layers)
__device__ int g_cnt[4][MAXN + 1];
__device__ int g_off[4][MAXN + 1];
__device__ int g_fill[4][MAXN + 1];
__device__ int g_ssrc[2 * EMT + 2 * EST];   // dst-sorted source indices
__device__ int g_bsum[4][128];

// ---------------- CSR build kernels ----------------
__global__ void hist_kernel(const int* __restrict__ dst, int* __restrict__ cnt, int E) {
    int i = blockIdx.x * blockDim.x + threadIdx.x;
    if (i < E) atomicAdd(&cnt[dst[i]], 1);
}

#define SCAN_BLOCK 1024
#define SCAN_ITEMS 2048

__global__ __launch_bounds__(SCAN_BLOCK) void scan1_kernel(
    const int* __restrict__ cnt, int* __restrict__ off, int* __restrict__ bsum, int n)
{
    __shared__ int wsum[32];
    int t = threadIdx.x;
    long base = (long)blockIdx.x * SCAN_ITEMS;
    long i0 = base + 2 * t, i1 = i0 + 1;
    int a0 = (i0 < n) ? cnt[i0] : 0;
    int a1 = (i1 < n) ? cnt[i1] : 0;
    int ts = a0 + a1;
    int lane = t & 31, w = t >> 5;
    int v = ts;
    #pragma unroll
    for (int o = 1; o < 32; o <<= 1) { int u = __shfl_up_sync(~0u, v, o); if (lane >= o) v += u; }
    if (lane == 31) wsum[w] = v;
    __syncthreads();
    if (w == 0) {
        int x = wsum[lane];
        #pragma unroll
        for (int o = 1; o < 32; o <<= 1) { int u = __shfl_up_sync(~0u, x, o); if (lane >= o) x += u; }
        wsum[lane] = x;
    }
    __syncthreads();
    int warp_prefix = (w == 0) ? 0 : wsum[w - 1];
    int excl = warp_prefix + (v - ts);
    if (i0 < n) off[i0] = excl;
    if (i1 < n) off[i1] = excl + a0;
    if (t == 0) bsum[blockIdx.x] = wsum[31];
}

__global__ void scan2_kernel(int* __restrict__ bsum, int nb) {
    __shared__ int ws[4];
    int t = threadIdx.x;   // 128
    int v = (t < nb) ? bsum[t] : 0;
    int lane = t & 31, w = t >> 5;
    int x = v;
    #pragma unroll
    for (int o = 1; o < 32; o <<= 1) { int u = __shfl_up_sync(~0u, x, o); if (lane >= o) x += u; }
    if (lane == 31) ws[w] = x;
    __syncthreads();
    if (t == 0) { int s = 0; for (int i = 0; i < 4; i++) { int c = ws[i]; ws[i] = s; s += c; } }
    __syncthreads();
    int excl = ws[w] + (x - v);
    if (t < nb) bsum[t] = excl;
}

__global__ void scan3_kernel(int* __restrict__ off, const int* __restrict__ bsum, int n) {
    long i = (long)blockIdx.x * blockDim.x + threadIdx.x;
    if (i < n) off[i] += bsum[i / SCAN_ITEMS];
}

__global__ void scatter_kernel(const int* __restrict__ dst, const int* __restrict__ src,
                               int* __restrict__ fill, int* __restrict__ ssrc, int E) {
    int i = blockIdx.x * blockDim.x + threadIdx.x;
    if (i < E) {
        int pos = atomicAdd(&fill[dst[i]], 1);
        ssrc[pos] = src[i];
    }
}

// ---------------- FFMA-bound GEMM core ----------------
// Block = 256 threads, 64 rows. Warp handles 8 rows (2 halves of 4).
// Lane li (0-15) owns output cols [li*4, li*4+4) as a float4 accumulator.
// sW holds W row-major (k-major) so no transpose; X broadcast per row.
// Per 4-k chunk per warp: 8 LDS vs 64 FFMA -> FFMA-issue bound.
// Variadic so commas in the X-load body pass through the preprocessor.

#define GEMM_PROLOGUE(...)                                                     \
    int t = threadIdx.x;                                                       \
    for (int i = t; i < 1024; i += 256) {                                      \
        int k = i >> 4, c4 = (i & 15) * 4;                                     \
        *(float4*)&sW[k * 68 + c4] = *(const float4*)(W + k * 64 + c4);        \
    }                                                                          \
    long r0 = (long)blockIdx.x * 64;                                           \
    __VA_ARGS__                                                                \
    __syncthreads();                                                           \
    int lane = t & 31, warp = t >> 5;                                          \
    int li = lane & 15, half = lane >> 4;                                      \
    int rbase = warp * 8 + half * 4;                                           \
    int c0 = li * 4;                                                           \
    float4 bv = *(const float4*)(bias + c0);                                   \
    float4 acc[4];                                                             \
    acc[0] = bv; acc[1] = bv; acc[2] = bv; acc[3] = bv;                        \
    _Pragma("unroll")                                                          \
    for (int k = 0; k < 64; k += 4) {                                          \
        float4 wv0 = *(float4*)&sW[(k + 0) * 68 + c0];                         \
        float4 wv1 = *(float4*)&sW[(k + 1) * 68 + c0];                         \
        float4 wv2 = *(float4*)&sW[(k + 2) * 68 + c0];                         \
        float4 wv3 = *(float4*)&sW[(k + 3) * 68 + c0];                         \
        _Pragma("unroll")                                                      \
        for (int r = 0; r < 4; r++) {                                          \
            float4 xv = *(float4*)&sX[(rbase + r) * 64 + k];                   \
            acc[r].x += xv.x * wv0.x + xv.y * wv1.x + xv.z * wv2.x + xv.w * wv3.x; \
            acc[r].y += xv.x * wv0.y + xv.y * wv1.y + xv.z * wv2.y + xv.w * wv3.y; \
            acc[r].z += xv.x * wv0.z + xv.y * wv1.z + xv.z * wv2.z + xv.w * wv3.z; \
            acc[r].w += xv.x * wv0.w + xv.y * wv1.w + xv.z * wv2.w + xv.w * wv3.w; \
        }                                                                      \
    }

// h = (blend of xA,xB) @ W + b ; plus up to 4 fused attention dot products.
__global__ __launch_bounds__(256) void proj_att_kernel(
    const float* __restrict__ xA, const float* __restrict__ xB,
    const float* __restrict__ wsem,
    const float* __restrict__ W, const float* __restrict__ bias,
    float* __restrict__ hout, int N,
    const float* av0, float* ao0, const float* av1, float* ao1,
    const float* av2, float* ao2, const float* av3, float* ao3)
{
    __shared__ float sW[64 * 68];
    __shared__ float sX[64 * 64];
    __shared__ float sAv[4 * 64];

    const float* avs[4] = {av0, av1, av2, av3};
    float*       aos[4] = {ao0, ao1, ao2, ao3};

    GEMM_PROLOGUE(
        if (t < 64) {
            for (int v = 0; v < 4; v++) if (avs[v]) sAv[v * 64 + t] = avs[v][t];
        }
        float wb0 = 1.f;
        float wb1 = 0.f;
        if (xB) { wb0 = wsem[0]; wb1 = wsem[1]; }
        for (int i = t; i < 1024; i += 256) {
            int r = i >> 4;
            int c4 = (i & 15) * 4;
            float4 v;
            v.x = 0.f; v.y = 0.f; v.z = 0.f; v.w = 0.f;
            if (r0 + r < N) {
                v = *(const float4*)(xA + (r0 + r) * 64 + c4);
                if (xB) {
                    float4 b2 = *(const float4*)(xB + (r0 + r) * 64 + c4);
                    v.x = wb0 * v.x + wb1 * b2.x;
                    v.y = wb0 * v.y + wb1 * b2.y;
                    v.z = wb0 * v.z + wb1 * b2.z;
                    v.w = wb0 * v.w + wb1 * b2.w;
                }
            }
            *(float4*)&sX[r * 64 + c4] = v;
        }
    )

    #pragma unroll
    for (int r = 0; r < 4; r++) {
        long row = r0 + rbase + r;
        if (row < N) *(float4*)(hout + row * 64 + c0) = acc[r];
    }

    // fused attention dots: per-head reduction over 8 lanes (head = li>>3)
    for (int v = 0; v < 4; v++) {
        if (!aos[v]) continue;
        float4 a4 = *(float4*)&sAv[v * 64 + c0];
        #pragma unroll
        for (int r = 0; r < 4; r++) {
            float p = acc[r].x * a4.x + acc[r].y * a4.y + acc[r].z * a4.z + acc[r].w * a4.w;
            p += __shfl_xor_sync(0xffffffffu, p, 1);
            p += __shfl_xor_sync(0xffffffffu, p, 2);
            p += __shfl_xor_sync(0xffffffffu, p, 4);
            long row = r0 + rbase + r;
            if ((li == 0 || li == 8) && row < N)
                aos[v][row * 2 + (li >> 3)] = p;
        }
    }
}

// acc_out[c] += sum_n tanh((o @ kW + kb)[n,c])
__global__ __launch_bounds__(256) void sem_reduce_kernel(
    const float* __restrict__ xA, const float* __restrict__ W,
    const float* __restrict__ bias, float* __restrict__ acc_out, int N)
{
    __shared__ float sW[64 * 68];
    __shared__ float sX[64 * 64];
    __shared__ float sAcc[64];

    GEMM_PROLOGUE(
        if (t < 64) sAcc[t] = 0.f;
        for (int i = t; i < 1024; i += 256) {
            int r = i >> 4;
            int c4 = (i & 15) * 4;
            float4 v;
            v.x = 0.f; v.y = 0.f; v.z = 0.f; v.w = 0.f;
            if (r0 + r < N) v = *(const float4*)(xA + (r0 + r) * 64 + c4);
            *(float4*)&sX[r * 64 + c4] = v;
        }
    )

    float4 s;
    s.x = 0.f; s.y = 0.f; s.z = 0.f; s.w = 0.f;
    #pragma unroll
    for (int r = 0; r < 4; r++) {
        if (r0 + rbase + r < N) {
            s.x += tanhf(acc[r].x);
            s.y += tanhf(acc[r].y);
            s.z += tanhf(acc[r].z);
            s.w += tanhf(acc[r].w);
        }
    }
    // reduce across the two halves (same cols), then half0 does shared atomics
    s.x += __shfl_xor_sync(0xffffffffu, s.x, 16);
    s.y += __shfl_xor_sync(0xffffffffu, s.y, 16);
    s.z += __shfl_xor_sync(0xffffffffu, s.z, 16);
    s.w += __shfl_xor_sync(0xffffffffu, s.w, 16);
    if (half == 0) {
        atomicAdd(&sAcc[c0 + 0], s.x);
        atomicAdd(&sAcc[c0 + 1], s.y);
        atomicAdd(&sAcc[c0 + 2], s.z);
        atomicAdd(&sAcc[c0 + 3], s.w);
    }
    __syncthreads();
    if (t < 64) atomicAdd(&acc_out[t], sAcc[t]);
}

// ---------------- CSR gather-aggregate kernel ----------------
__global__ __launch_bounds__(256) void edge_gather_kernel(
    const int* __restrict__ ssrc, const int* __restrict__ off,
    const float* __restrict__ as, const float* __restrict__ ad,
    const float* __restrict__ h, float* __restrict__ out, int N)
{
    int warp = (int)(((long)blockIdx.x * blockDim.x + threadIdx.x) >> 5);
    int lane = threadIdx.x & 31;
    if (warp >= N) return;
    int d = warp;
    int beg = off[d], end = off[d + 1];
    int head = lane >> 4;

    float2 adv = *(const float2*)(ad + (long)d * 2);
    float accx = 0.f, accy = 0.f, se0 = 0.f, se1 = 0.f;

    for (int base = beg; base < end; base += 32) {
        int idx = base + lane;
        int s = 0;
        float ex0 = 0.f, ex1 = 0.f;
        if (idx < end) {
            s = ssrc[idx];
            float2 av = *(const float2*)(as + (long)s * 2);
            float l0 = av.x + adv.x; l0 = (l0 >= 0.f) ? l0 : 0.2f * l0;
            float l1 = av.y + adv.y; l1 = (l1 >= 0.f) ? l1 : 0.2f * l1;
            ex0 = __expf(l0); ex1 = __expf(l1);
            se0 += ex0; se1 += ex1;
        }
        int cnt = min(32, end - base);
        for (int i = 0; i < cnt; i++) {
            int si  = __shfl_sync(0xffffffffu, s, i);
            float e0 = __shfl_sync(0xffffffffu, ex0, i);
            float e1 = __shfl_sync(0xffffffffu, ex1, i);
            float exl = head ? e1 : e0;
            float2 hv = *(const float2*)(h + (long)si * 64 + lane * 2);
            accx += exl * hv.x;
            accy += exl * hv.y;
        }
    }

    #pragma unroll
    for (int o = 16; o; o >>= 1) {
        se0 += __shfl_xor_sync(0xffffffffu, se0, o);
        se1 += __shfl_xor_sync(0xffffffffu, se1, o);
    }
    float inv = 1.0f / ((head ? se1 : se0) + 1e-16f);
    accx = fmaxf(accx * inv, 0.f);
    accy = fmaxf(accy * inv, 0.f);
    *(float2*)(out + (long)d * 64 + lane * 2) = make_float2(accx, accy);
}

// ---------------- semantic finalize ----------------
__global__ void sem_finalize_kernel(const float* __restrict__ acc, const float* __restrict__ q,
                                    float* __restrict__ wout)
{
    __shared__ float s0[64], s1[64];
    int t = threadIdx.x;
    s0[t] = q[t] * acc[t]      * (1.0f / NT);
    s1[t] = q[t] * acc[64 + t] * (1.0f / NT);
    __syncthreads();
    if (t == 0) {
        float a = 0.f, b = 0.f;
        for (int i = 0; i < 64; i++) { a += s0[i]; b += s1[i]; }
        float m = fmaxf(a, b);
        float e0 = __expf(a - m), e1 = __expf(b - m);
        float inv = 1.0f / (e0 + e1);
        wout[0] = e0 * inv;
        wout[1] = e1 * inv;
    }
}

// ---------------- host orchestration ----------------
extern "C" void kernel_launch(void* const* d_in, const int* in_sizes, int n_in,
                              void* d_out, int out_size)
{
    (void)in_sizes; (void)n_in; (void)out_size;
    const float* x_m  = (const float*)d_in[0];
    const float* x_s  = (const float*)d_in[1];
    const float* x_t  = (const float*)d_in[2];
    const int* esrc[4] = {(const int*)d_in[3], (const int*)d_in[5], (const int*)d_in[7], (const int*)d_in[9]};
    const int* edst[4] = {(const int*)d_in[4], (const int*)d_in[6], (const int*)d_in[8], (const int*)d_in[10]};
    const float* Wp   = (const float*)d_in[11];
    const float* bp   = (const float*)d_in[12];
    const float* aS   = (const float*)d_in[13];
    const float* aD   = (const float*)d_in[14];
    const float* kWp  = (const float*)d_in[15];
    const float* kbp  = (const float*)d_in[16];
    const float* qp   = (const float*)d_in[17];
    const float* linW = (const float*)d_in[18];
    const float* linb = (const float*)d_in[19];
    float* out = (float*)d_out;

    float *h0, *h1, *h2, *o0, *o1, *oT0, *oT1, *acc, *wsem, *asb, *adb;
    int *cntb, *offb, *fillb, *ssrcb, *bsumb;
    cudaGetSymbolAddress((void**)&h0,  g_h0);
    cudaGetSymbolAddress((void**)&h1,  g_h1);
    cudaGetSymbolAddress((void**)&h2,  g_h2);
    cudaGetSymbolAddress((void**)&o0,  g_o0);
    cudaGetSymbolAddress((void**)&o1,  g_o1);
    cudaGetSymbolAddress((void**)&oT0, g_oT0);
    cudaGetSymbolAddress((void**)&oT1, g_oT1);
    cudaGetSymbolAddress((void**)&acc, g_acc);
    cudaGetSymbolAddress((void**)&wsem, g_w);
    cudaGetSymbolAddress((void**)&asb, g_as);
    cudaGetSymbolAddress((void**)&adb, g_ad);
    cudaGetSymbolAddress((void**)&cntb, g_cnt);
    cudaGetSymbolAddress((void**)&offb, g_off);
    cudaGetSymbolAddress((void**)&fillb, g_fill);
    cudaGetSymbolAddress((void**)&ssrcb, g_ssrc);
    cudaGetSymbolAddress((void**)&bsumb, g_bsum);

    float* as_[4]; float* ad_[4];
    int* cnt_[4]; int* off_[4]; int* fill_[4]; int* ssrc_[4]; int* bsum_[4];
    const long permoff[4] = {0, EMT, 2L * EMT, 2L * EMT + EST};
    for (int e = 0; e < 4; e++) {
        as_[e]   = asb + (long)e * MAXN * 2;
        ad_[e]   = adb + (long)e * MAXN * 2;
        cnt_[e]  = cntb  + (long)e * (MAXN + 1);
        off_[e]  = offb  + (long)e * (MAXN + 1);
        fill_[e] = fillb + (long)e * (MAXN + 1);
        bsum_[e] = bsumb + (long)e * 128;
        ssrc_[e] = ssrcb + permoff[e];
    }

    const int EN[4] = {EMT, EMT, EST, EST};
    const int ND[4] = {NT, NM, NT, NS};
    float* AGG[4] = {oT0, o0, oT1, o1};

    // ---- build CSR once (reused across all 3 layers) ----
    for (int e = 0; e < 4; e++) {
        int n = ND[e], E = EN[e];
        int nscan = n + 1;
        int nb = (nscan + SCAN_ITEMS - 1) / SCAN_ITEMS;
        cudaMemsetAsync(cnt_[e], 0, (size_t)nscan * sizeof(int));
        hist_kernel<<<(E + 255) / 256, 256>>>(edst[e], cnt_[e], E);
        scan1_kernel<<<nb, SCAN_BLOCK>>>(cnt_[e], off_[e], bsum_[e], nscan);
        scan2_kernel<<<1, 128>>>(bsum_[e], nb);
        scan3_kernel<<<(nscan + 255) / 256, 256>>>(off_[e], bsum_[e], nscan);
        cudaMemcpyAsync(fill_[e], off_[e], (size_t)nscan * sizeof(int),
                        cudaMemcpyDeviceToDevice);
        scatter_kernel<<<(E + 255) / 256, 256>>>(edst[e], esrc[e], fill_[e], ssrc_[e], E);
    }

    for (int l = 0; l < 3; l++) {
        const float* xm = l ? o0 : x_m;
        const float* xs = l ? o1 : x_s;
        const float* xtA = l ? oT0 : x_t;
        const float* xtB = l ? oT1 : nullptr;

        const float* W0 = Wp + (long)(l * 3 + 0) * 4096;
        const float* W1 = Wp + (long)(l * 3 + 1) * 4096;
        const float* W2 = Wp + (long)(l * 3 + 2) * 4096;
        const float* b0 = bp + (long)(l * 3 + 0) * 64;
        const float* b1 = bp + (long)(l * 3 + 1) * 64;
        const float* b2 = bp + (long)(l * 3 + 2) * 64;

        proj_att_kernel<<<(NM + 63) / 64, 256>>>(xm, nullptr, wsem, W0, b0, h0, NM,
            aS + (long)(l * 4 + 0) * 64, as_[0],
            aD + (long)(l * 4 + 1) * 64, ad_[1],
            nullptr, nullptr, nullptr, nullptr);
        proj_att_kernel<<<(NS + 63) / 64, 256>>>(xs, nullptr, wsem, W1, b1, h1, NS,
            aS + (long)(l * 4 + 2) * 64, as_[2],
            aD + (long)(l * 4 + 3) * 64, ad_[3],
            nullptr, nullptr, nullptr, nullptr);
        proj_att_kernel<<<(NT + 63) / 64, 256>>>(xtA, xtB, wsem, W2, b2, h2, NT,
            aS + (long)(l * 4 + 1) * 64, as_[1],
            aS + (long)(l * 4 + 3) * 64, as_[3],
            aD + (long)(l * 4 + 0) * 64, ad_[0],
            aD + (long)(l * 4 + 2) * 64, ad_[2]);

        const float* HS[4] = {h0, h2, h1, h2};
        for (int e = 0; e < 4; e++) {
            int n = ND[e];
            long thr = (long)n * 32;
            edge_gather_kernel<<<(unsigned)((thr + 255) / 256), 256>>>(
                ssrc_[e], off_[e], as_[e], ad_[e], HS[e], AGG[e], n);
        }

        cudaMemsetAsync(acc, 0, 128 * sizeof(float));
        sem_reduce_kernel<<<(NT + 63) / 64, 256>>>(oT0, kWp + (long)l * 4096, kbp + (long)l * 64, acc,      NT);
        sem_reduce_kernel<<<(NT + 63) / 64, 256>>>(oT1, kWp + (long)l * 4096, kbp + (long)l * 64, acc + 64, NT);
        sem_finalize_kernel<<<1, 64>>>(acc, qp + (long)l * 64, wsem);
    }

    // final shared linear, writing straight into d_out (member, skill, team order)
    proj_att_kernel<<<(NM + 63) / 64, 256>>>(o0, nullptr, wsem, linW, linb, out, NM,
        nullptr, nullptr, nullptr, nullptr, nullptr, nullptr, nullptr, nullptr);
    proj_att_kernel<<<(NS + 63) / 64, 256>>>(o1, nullptr, wsem, linW, linb, out + (long)NM * CC, NS,
        nullptr, nullptr, nullptr, nullptr, nullptr, nullptr, nullptr, nullptr);
    proj_att_kernel<<<(NT + 63) / 64, 256>>>(oT0, oT1, wsem, linW, linb, out + (long)(NM + NS) * CC, NT,
        nullptr, nullptr, nullptr, nullptr, nullptr, nullptr, nullptr, nullptr);
}

// round 8
// speedup vs baseline: 1.2779x; 1.2779x over previous
#include <cuda_runtime.h>
#include <math.h>

// Problem constants
#define NM 100000
#define NS 20000
#define NT 200000
#define CC 64
#define EMT 1000000
#define EST 500000
#define MAXN NT

// ---------------- static device scratch ----------------
__device__ float g_h0[NM * CC];
__device__ float g_h1[NS * CC];
__device__ float g_h2[NT * CC];
__device__ float g_o0[NM * CC];
__device__ float g_o1[NS * CC];
__device__ float g_oT0[NT * CC];
__device__ float g_oT1[NT * CC];
__device__ float g_as[4][MAXN * 2];
__device__ float g_ad[4][MAXN * 2];
__device__ float g_acc[2 * CC];
__device__ float g_w[2];

// CSR scratch (built once per call, reused across 3 layers)
__device__ int g_cnt[4][MAXN + 1];
__device__ int g_off[4][MAXN + 1];
__device__ int g_fill[4][MAXN + 1];
__device__ int g_ssrc[2 * EMT + 2 * EST];   // dst-sorted source indices
__device__ int g_bsum[4][128];

__device__ __forceinline__ float fast_tanh(float x) {
    float y;
    asm("tanh.approx.f32 %0, %1;" : "=f"(y) : "f"(x));
    return y;
}

// ---------------- CSR build kernels ----------------
__global__ void hist_kernel(const int* __restrict__ dst, int* __restrict__ cnt, int E) {
    int i = blockIdx.x * blockDim.x + threadIdx.x;
    if (i < E) atomicAdd(&cnt[dst[i]], 1);
}

#define SCAN_BLOCK 1024
#define SCAN_ITEMS 2048

__global__ __launch_bounds__(SCAN_BLOCK) void scan1_kernel(
    const int* __restrict__ cnt, int* __restrict__ off, int* __restrict__ bsum, int n)
{
    __shared__ int wsum[32];
    int t = threadIdx.x;
    long base = (long)blockIdx.x * SCAN_ITEMS;
    long i0 = base + 2 * t, i1 = i0 + 1;
    int a0 = (i0 < n) ? cnt[i0] : 0;
    int a1 = (i1 < n) ? cnt[i1] : 0;
    int ts = a0 + a1;
    int lane = t & 31, w = t >> 5;
    int v = ts;
    #pragma unroll
    for (int o = 1; o < 32; o <<= 1) { int u = __shfl_up_sync(~0u, v, o); if (lane >= o) v += u; }
    if (lane == 31) wsum[w] = v;
    __syncthreads();
    if (w == 0) {
        int x = wsum[lane];
        #pragma unroll
        for (int o = 1; o < 32; o <<= 1) { int u = __shfl_up_sync(~0u, x, o); if (lane >= o) x += u; }
        wsum[lane] = x;
    }
    __syncthreads();
    int warp_prefix = (w == 0) ? 0 : wsum[w - 1];
    int excl = warp_prefix + (v - ts);
    if (i0 < n) off[i0] = excl;
    if (i1 < n) off[i1] = excl + a0;
    if (t == 0) bsum[blockIdx.x] = wsum[31];
}

__global__ void scan2_kernel(int* __restrict__ bsum, int nb) {
    __shared__ int ws[4];
    int t = threadIdx.x;   // 128
    int v = (t < nb) ? bsum[t] : 0;
    int lane = t & 31, w = t >> 5;
    int x = v;
    #pragma unroll
    for (int o = 1; o < 32; o <<= 1) { int u = __shfl_up_sync(~0u, x, o); if (lane >= o) x += u; }
    if (lane == 31) ws[w] = x;
    __syncthreads();
    if (t == 0) { int s = 0; for (int i = 0; i < 4; i++) { int c = ws[i]; ws[i] = s; s += c; } }
    __syncthreads();
    int excl = ws[w] + (x - v);
    if (t < nb) bsum[t] = excl;
}

__global__ void scan3_kernel(int* __restrict__ off, const int* __restrict__ bsum, int n) {
    long i = (long)blockIdx.x * blockDim.x + threadIdx.x;
    if (i < n) off[i] += bsum[i / SCAN_ITEMS];
}

__global__ void scatter_kernel(const int* __restrict__ dst, const int* __restrict__ src,
                               int* __restrict__ fill, int* __restrict__ ssrc, int E) {
    int i = blockIdx.x * blockDim.x + threadIdx.x;
    if (i < E) {
        int pos = atomicAdd(&fill[dst[i]], 1);
        ssrc[pos] = src[i];
    }
}

// ---------------- fused projection + attention-dot kernel (round-4 GEMM core) ----------------
__global__ __launch_bounds__(256) void proj_att_kernel(
    const float* __restrict__ xA, const float* __restrict__ xB,
    const float* __restrict__ wsem,
    const float* __restrict__ W, const float* __restrict__ bias,
    float* __restrict__ hout, int N,
    const float* av0, float* ao0, const float* av1, float* ao1,
    const float* av2, float* ao2, const float* av3, float* ao3)
{
    __shared__ float sWt[64 * 68];
    __shared__ float sAv[4 * 64];
    __shared__ float sX[8][512];

    const float* avs[4] = {av0, av1, av2, av3};
    float*       aos[4] = {ao0, ao1, ao2, ao3};

    int t = threadIdx.x;
    for (int i = t; i < 4096; i += 256) { int k = i >> 6, c = i & 63; sWt[c * 68 + k] = W[i]; }
    if (t < 64) {
        #pragma unroll
        for (int v = 0; v < 4; v++) if (avs[v]) sAv[v * 64 + t] = avs[v][t];
    }
    __syncthreads();

    int lane = t & 31, slot = t >> 5;
    long r0 = (long)blockIdx.x * 64 + slot * 8;

    float w0 = 1.f, w1 = 0.f;
    if (xB) { w0 = wsem[0]; w1 = wsem[1]; }

    for (int j = lane; j < 128; j += 32) {
        int r = j >> 4, kk = (j & 15) * 4;
        float4 vv = make_float4(0.f, 0.f, 0.f, 0.f);
        if (r0 + r < N) {
            vv = *(const float4*)(xA + (r0 + r) * 64 + kk);
            if (xB) {
                float4 vb = *(const float4*)(xB + (r0 + r) * 64 + kk);
                vv.x = w0 * vv.x + w1 * vb.x;
                vv.y = w0 * vv.y + w1 * vb.y;
                vv.z = w0 * vv.z + w1 * vb.z;
                vv.w = w0 * vv.w + w1 * vb.w;
            }
        }
        *(float4*)&sX[slot][r * 64 + kk] = vv;
    }
    __syncwarp();

    float b0 = bias[lane], b1 = bias[lane + 32];
    float acc0[8], acc1[8];
    #pragma unroll
    for (int r = 0; r < 8; r++) { acc0[r] = b0; acc1[r] = b1; }

    #pragma unroll
    for (int k = 0; k < 64; k += 4) {
        float4 wv0 = *(const float4*)&sWt[lane * 68 + k];
        float4 wv1 = *(const float4*)&sWt[(lane + 32) * 68 + k];
        #pragma unroll
        for (int r = 0; r < 8; r++) {
            float4 xv = *(const float4*)&sX[slot][r * 64 + k];
            acc0[r] += xv.x * wv0.x + xv.y * wv0.y + xv.z * wv0.z + xv.w * wv0.w;
            acc1[r] += xv.x * wv1.x + xv.y * wv1.y + xv.z * wv1.z + xv.w * wv1.w;
        }
    }

    #pragma unroll
    for (int r = 0; r < 8; r++) {
        if (r0 + r < N) {
            hout[(r0 + r) * 64 + lane]      = acc0[r];
            hout[(r0 + r) * 64 + lane + 32] = acc1[r];
        }
    }

    for (int v = 0; v < 4; v++) {
        if (!aos[v]) continue;
        float a0v = sAv[v * 64 + lane], a1v = sAv[v * 64 + lane + 32];
        #pragma unroll
        for (int r = 0; r < 8; r++) {
            float p0 = acc0[r] * a0v;
            float p1 = acc1[r] * a1v;
            #pragma unroll
            for (int off = 16; off; off >>= 1) {
                p0 += __shfl_xor_sync(0xffffffffu, p0, off);
                p1 += __shfl_xor_sync(0xffffffffu, p1, off);
            }
            if (lane == 0 && r0 + r < N) {
                aos[v][(r0 + r) * 2]     = p0;
                aos[v][(r0 + r) * 2 + 1] = p1;
            }
        }
    }
}

// acc_out[c] += sum_n tanh((o @ kW + kb)[n,c])
__global__ __launch_bounds__(256) void sem_reduce_kernel(
    const float* __restrict__ o, const float* __restrict__ W,
    const float* __restrict__ bias, float* __restrict__ acc_out, int N)
{
    __shared__ float sWt[64 * 68];
    __shared__ float sX[8][512];
    __shared__ float sAcc[64];

    int t = threadIdx.x;
    for (int i = t; i < 4096; i += 256) { int k = i >> 6, c = i & 63; sWt[c * 68 + k] = W[i]; }
    if (t < 64) sAcc[t] = 0.f;
    __syncthreads();

    int lane = t & 31, slot = t >> 5;
    long r0 = (long)blockIdx.x * 64 + slot * 8;

    for (int j = lane; j < 128; j += 32) {
        int r = j >> 4, kk = (j & 15) * 4;
        float4 vv = make_float4(0.f, 0.f, 0.f, 0.f);
        if (r0 + r < N) vv = *(const float4*)(o + (r0 + r) * 64 + kk);
        *(float4*)&sX[slot][r * 64 + kk] = vv;
    }
    __syncwarp();

    float b0 = bias[lane], b1 = bias[lane + 32];
    float acc0[8], acc1[8];
    #pragma unroll
    for (int r = 0; r < 8; r++) { acc0[r] = b0; acc1[r] = b1; }

    #pragma unroll
    for (int k = 0; k < 64; k += 4) {
        float4 w0 = *(const float4*)&sWt[lane * 68 + k];
        float4 w1 = *(const float4*)&sWt[(lane + 32) * 68 + k];
        #pragma unroll
        for (int r = 0; r < 8; r++) {
            float4 xv = *(const float4*)&sX[slot][r * 64 + k];
            acc0[r] += xv.x * w0.x + xv.y * w0.y + xv.z * w0.z + xv.w * w0.w;
            acc1[r] += xv.x * w1.x + xv.y * w1.y + xv.z * w1.z + xv.w * w1.w;
        }
    }

    float s0 = 0.f, s1 = 0.f;
    #pragma unroll
    for (int r = 0; r < 8; r++) {
        if (r0 + r < N) { s0 += fast_tanh(acc0[r]); s1 += fast_tanh(acc1[r]); }
    }
    atomicAdd(&sAcc[lane], s0);
    atomicAdd(&sAcc[lane + 32], s1);
    __syncthreads();
    if (t < 64) atomicAdd(&acc_out[t], sAcc[t]);
}

// ---------------- CSR gather-aggregate kernel ----------------
__global__ __launch_bounds__(256) void edge_gather_kernel(
    const int* __restrict__ ssrc, const int* __restrict__ off,
    const float* __restrict__ as, const float* __restrict__ ad,
    const float* __restrict__ h, float* __restrict__ out, int N)
{
    int warp = (int)(((long)blockIdx.x * blockDim.x + threadIdx.x) >> 5);
    int lane = threadIdx.x & 31;
    if (warp >= N) return;
    int d = warp;
    int beg = off[d], end = off[d + 1];
    int head = lane >> 4;

    float2 adv = *(const float2*)(ad + (long)d * 2);
    float accx = 0.f, accy = 0.f, se0 = 0.f, se1 = 0.f;

    for (int base = beg; base < end; base += 32) {
        int idx = base + lane;
        int s = 0;
        float ex0 = 0.f, ex1 = 0.f;
        if (idx < end) {
            s = ssrc[idx];
            float2 av = *(const float2*)(as + (long)s * 2);
            float l0 = av.x + adv.x; l0 = (l0 >= 0.f) ? l0 : 0.2f * l0;
            float l1 = av.y + adv.y; l1 = (l1 >= 0.f) ? l1 : 0.2f * l1;
            ex0 = __expf(l0); ex1 = __expf(l1);
            se0 += ex0; se1 += ex1;
        }
        int cnt = min(32, end - base);
        for (int i = 0; i < cnt; i++) {
            int si  = __shfl_sync(0xffffffffu, s, i);
            float e0 = __shfl_sync(0xffffffffu, ex0, i);
            float e1 = __shfl_sync(0xffffffffu, ex1, i);
            float exl = head ? e1 : e0;
            float2 hv = *(const float2*)(h + (long)si * 64 + lane * 2);
            accx += exl * hv.x;
            accy += exl * hv.y;
        }
    }

    #pragma unroll
    for (int o = 16; o; o >>= 1) {
        se0 += __shfl_xor_sync(0xffffffffu, se0, o);
        se1 += __shfl_xor_sync(0xffffffffu, se1, o);
    }
    float inv = 1.0f / ((head ? se1 : se0) + 1e-16f);
    accx = fmaxf(accx * inv, 0.f);
    accy = fmaxf(accy * inv, 0.f);
    *(float2*)(out + (long)d * 64 + lane * 2) = make_float2(accx, accy);
}

// ---------------- semantic finalize ----------------
__global__ void sem_finalize_kernel(const float* __restrict__ acc, const float* __restrict__ q,
                                    float* __restrict__ wout)
{
    __shared__ float s0[64], s1[64];
    int t = threadIdx.x;
    s0[t] = q[t] * acc[t]      * (1.0f / NT);
    s1[t] = q[t] * acc[64 + t] * (1.0f / NT);
    __syncthreads();
    if (t == 0) {
        float a = 0.f, b = 0.f;
        for (int i = 0; i < 64; i++) { a += s0[i]; b += s1[i]; }
        float m = fmaxf(a, b);
        float e0 = __expf(a - m), e1 = __expf(b - m);
        float inv = 1.0f / (e0 + e1);
        wout[0] = e0 * inv;
        wout[1] = e1 * inv;
    }
}

// ---------------- host orchestration ----------------
extern "C" void kernel_launch(void* const* d_in, const int* in_sizes, int n_in,
                              void* d_out, int out_size)
{
    (void)in_sizes; (void)n_in; (void)out_size;
    const float* x_m  = (const float*)d_in[0];
    const float* x_s  = (const float*)d_in[1];
    const float* x_t  = (const float*)d_in[2];
    const int* esrc[4] = {(const int*)d_in[3], (const int*)d_in[5], (const int*)d_in[7], (const int*)d_in[9]};
    const int* edst[4] = {(const int*)d_in[4], (const int*)d_in[6], (const int*)d_in[8], (const int*)d_in[10]};
    const float* Wp   = (const float*)d_in[11];
    const float* bp   = (const float*)d_in[12];
    const float* aS   = (const float*)d_in[13];
    const float* aD   = (const float*)d_in[14];
    const float* kWp  = (const float*)d_in[15];
    const float* kbp  = (const float*)d_in[16];
    const float* qp   = (const float*)d_in[17];
    const float* linW = (const float*)d_in[18];
    const float* linb = (const float*)d_in[19];
    float* out = (float*)d_out;

    float *h0, *h1, *h2, *o0, *o1, *oT0, *oT1, *acc, *wsem, *asb, *adb;
    int *cntb, *offb, *fillb, *ssrcb, *bsumb;
    cudaGetSymbolAddress((void**)&h0,  g_h0);
    cudaGetSymbolAddress((void**)&h1,  g_h1);
    cudaGetSymbolAddress((void**)&h2,  g_h2);
    cudaGetSymbolAddress((void**)&o0,  g_o0);
    cudaGetSymbolAddress((void**)&o1,  g_o1);
    cudaGetSymbolAddress((void**)&oT0, g_oT0);
    cudaGetSymbolAddress((void**)&oT1, g_oT1);
    cudaGetSymbolAddress((void**)&acc, g_acc);
    cudaGetSymbolAddress((void**)&wsem, g_w);
    cudaGetSymbolAddress((void**)&asb, g_as);
    cudaGetSymbolAddress((void**)&adb, g_ad);
    cudaGetSymbolAddress((void**)&cntb, g_cnt);
    cudaGetSymbolAddress((void**)&offb, g_off);
    cudaGetSymbolAddress((void**)&fillb, g_fill);
    cudaGetSymbolAddress((void**)&ssrcb, g_ssrc);
    cudaGetSymbolAddress((void**)&bsumb, g_bsum);

    float* as_[4]; float* ad_[4];
    int* cnt_[4]; int* off_[4]; int* fill_[4]; int* ssrc_[4]; int* bsum_[4];
    const long permoff[4] = {0, EMT, 2L * EMT, 2L * EMT + EST};
    for (int e = 0; e < 4; e++) {
        as_[e]   = asb + (long)e * MAXN * 2;
        ad_[e]   = adb + (long)e * MAXN * 2;
        cnt_[e]  = cntb  + (long)e * (MAXN + 1);
        off_[e]  = offb  + (long)e * (MAXN + 1);
        fill_[e] = fillb + (long)e * (MAXN + 1);
        bsum_[e] = bsumb + (long)e * 128;
        ssrc_[e] = ssrcb + permoff[e];
    }

    const int EN[4] = {EMT, EMT, EST, EST};
    const int ND[4] = {NT, NM, NT, NS};
    float* AGG[4] = {oT0, o0, oT1, o1};

    // ---- build CSR once (reused across all 3 layers) ----
    for (int e = 0; e < 4; e++) {
        int n = ND[e], E = EN[e];
        int nscan = n + 1;
        int nb = (nscan + SCAN_ITEMS - 1) / SCAN_ITEMS;
        cudaMemsetAsync(cnt_[e], 0, (size_t)nscan * sizeof(int));
        hist_kernel<<<(E + 255) / 256, 256>>>(edst[e], cnt_[e], E);
        scan1_kernel<<<nb, SCAN_BLOCK>>>(cnt_[e], off_[e], bsum_[e], nscan);
        scan2_kernel<<<1, 128>>>(bsum_[e], nb);
        scan3_kernel<<<(nscan + 255) / 256, 256>>>(off_[e], bsum_[e], nscan);
        cudaMemcpyAsync(fill_[e], off_[e], (size_t)nscan * sizeof(int),
                        cudaMemcpyDeviceToDevice);
        scatter_kernel<<<(E + 255) / 256, 256>>>(edst[e], esrc[e], fill_[e], ssrc_[e], E);
    }

    for (int l = 0; l < 3; l++) {
        const float* xm = l ? o0 : x_m;
        const float* xs = l ? o1 : x_s;
        const float* xtA = l ? oT0 : x_t;
        const float* xtB = l ? oT1 : nullptr;

        const float* W0 = Wp + (long)(l * 3 + 0) * 4096;
        const float* W1 = Wp + (long)(l * 3 + 1) * 4096;
        const float* W2 = Wp + (long)(l * 3 + 2) * 4096;
        const float* b0 = bp + (long)(l * 3 + 0) * 64;
        const float* b1 = bp + (long)(l * 3 + 1) * 64;
        const float* b2 = bp + (long)(l * 3 + 2) * 64;

        proj_att_kernel<<<(NM + 63) / 64, 256>>>(xm, nullptr, wsem, W0, b0, h0, NM,
            aS + (long)(l * 4 + 0) * 64, as_[0],
            aD + (long)(l * 4 + 1) * 64, ad_[1],
            nullptr, nullptr, nullptr, nullptr);
        proj_att_kernel<<<(NS + 63) / 64, 256>>>(xs, nullptr, wsem, W1, b1, h1, NS,
            aS + (long)(l * 4 + 2) * 64, as_[2],
            aD + (long)(l * 4 + 3) * 64, ad_[3],
            nullptr, nullptr, nullptr, nullptr);
        proj_att_kernel<<<(NT + 63) / 64, 256>>>(xtA, xtB, wsem, W2, b2, h2, NT,
            aS + (long)(l * 4 + 1) * 64, as_[1],
            aS + (long)(l * 4 + 3) * 64, as_[3],
            aD + (long)(l * 4 + 0) * 64, ad_[0],
            aD + (long)(l * 4 + 2) * 64, ad_[2]);

        const float* HS[4] = {h0, h2, h1, h2};
        for (int e = 0; e < 4; e++) {
            int n = ND[e];
            long thr = (long)n * 32;
            edge_gather_kernel<<<(unsigned)((thr + 255) / 256), 256>>>(
                ssrc_[e], off_[e], as_[e], ad_[e], HS[e], AGG[e], n);
        }

        cudaMemsetAsync(acc, 0, 128 * sizeof(float));
        sem_reduce_kernel<<<(NT + 63) / 64, 256>>>(oT0, kWp + (long)l * 4096, kbp + (long)l * 64, acc,      NT);
        sem_reduce_kernel<<<(NT + 63) / 64, 256>>>(oT1, kWp + (long)l * 4096, kbp + (long)l * 64, acc + 64, NT);
        sem_finalize_kernel<<<1, 64>>>(acc, qp + (long)l * 64, wsem);
    }

    // final shared linear, writing straight into d_out (member, skill, team order)
    proj_att_kernel<<<(NM + 63) / 64, 256>>>(o0, nullptr, wsem, linW, linb, out, NM,
        nullptr, nullptr, nullptr, nullptr, nullptr, nullptr, nullptr, nullptr);
    proj_att_kernel<<<(NS + 63) / 64, 256>>>(o1, nullptr, wsem, linW, linb, out + (long)NM * CC, NS,
        nullptr, nullptr, nullptr, nullptr, nullptr, nullptr, nullptr, nullptr);
    proj_att_kernel<<<(NT + 63) / 64, 256>>>(oT0, oT1, wsem, linW, linb, out + (long)(NM + NS) * CC, NT,
        nullptr, nullptr, nullptr, nullptr, nullptr, nullptr, nullptr, nullptr);
}